// round 14
// baseline (speedup 1.0000x reference)
#include <cuda_runtime.h>
#include <math_constants.h>

#define NPIX_MAX (32 * 128 * 2048)
#define TB   256
#define OCC  8
#define GRID (148 * OCC)   // 1184, co-resident at 8 CTAs/SM

__device__ float        g_gray[NPIX_MAX];
__device__ unsigned int g_min_bits;
__device__ unsigned int g_max_bits;
__device__ unsigned int g_hist[256];
__device__ unsigned int g_bar;

__device__ __forceinline__ unsigned int f_enc(float f) {
    unsigned int u = __float_as_uint(f);
    return (u & 0x80000000u) ? ~u : (u | 0x80000000u);
}
__device__ __forceinline__ float f_dec(unsigned int e) {
    unsigned int u = (e & 0x80000000u) ? (e & 0x7FFFFFFFu) : ~e;
    return __uint_as_float(u);
}
__device__ __forceinline__ float gray_of(float r, float g, float b) {
    return fmaf(0.1140f, b, fmaf(0.5870f, g, __fmul_rn(0.2989f, r)));
}

// monotonic counter barrier; counter reset ONLY by init_kernel (no races)
__device__ __forceinline__ void grid_barrier(unsigned int target) {
    __syncthreads();
    if (threadIdx.x == 0) {
        __threadfence();
        atomicAdd(&g_bar, 1u);
        while (*((volatile unsigned int*)&g_bar) < target) __nanosleep(32);
        __threadfence();
    }
    __syncthreads();
}

// ---------------- K0: reset state (inside graph, every replay) -------------
__global__ void init_kernel() {
    int t = threadIdx.x;
    if (t < 256) g_hist[t] = 0u;
    if (t == 0) {
        g_min_bits = 0xFFFFFFFFu;
        g_max_bits = 0x00000000u;
        g_bar      = 0u;
    }
}

struct SharedU {
    union {
        float4       stage[TB * 3];     // 12 KB: phase 1
        unsigned int hist[256 * 8];     //  8 KB: phase 2
        struct {
            float c[256], w1[256], s1[256], w2[256], s2[256], bv[256];
            int bi[256];
        } o;                             //  7 KB: phase 3
    };
};

// ---------------- fused persistent kernel (OCC 8) --------------------------
__global__ void __launch_bounds__(TB, OCC)
fused_kernel(const float* __restrict__ in, float* __restrict__ out, int npix) {
    __shared__ SharedU sh;
    __shared__ float smin[8], smax[8];
    __shared__ float s_thresh;

    const int t       = threadIdx.x;
    const unsigned G  = gridDim.x;
    const int ngroups = npix >> 2;
    const int nf4     = ngroups * 3;
    const int ntiles  = (ngroups + TB - 1) / TB;
    const int gstride = G * TB;

    // ================= phase 1: gray + min/max (staged, proven) =========
    {
        const float4* __restrict__ in4 = (const float4*)in;
        float4* __restrict__ gr4 = (float4*)g_gray;
        float lmin = CUDART_INF_F, lmax = -CUDART_INF_F;

        for (int tile = blockIdx.x; tile < ntiles; tile += G) {
            const int gbase = tile * TB;
            const int fbase = gbase * 3;
            #pragma unroll
            for (int j = 0; j < 3; j++) {
                int idx = t + j * TB;
                if (fbase + idx < nf4) sh.stage[idx] = in4[fbase + idx];
            }
            __syncthreads();
            const int g = gbase + t;
            if (g < ngroups) {
                float4 a = sh.stage[3 * t + 0];
                float4 b = sh.stage[3 * t + 1];
                float4 c = sh.stage[3 * t + 2];
                float g0 = gray_of(a.x, a.y, a.z);
                float g1 = gray_of(a.w, b.x, b.y);
                float g2 = gray_of(b.z, b.w, c.x);
                float g3 = gray_of(c.y, c.z, c.w);
                gr4[g] = make_float4(g0, g1, g2, g3);
                lmin = fminf(lmin, fminf(fminf(g0, g1), fminf(g2, g3)));
                lmax = fmaxf(lmax, fmaxf(fmaxf(g0, g1), fmaxf(g2, g3)));
            }
            __syncthreads();
        }
        for (int p = (ngroups << 2) + blockIdx.x * TB + t; p < npix; p += gstride) {
            float gg = gray_of(in[3 * p], in[3 * p + 1], in[3 * p + 2]);
            g_gray[p] = gg;
            lmin = fminf(lmin, gg);
            lmax = fmaxf(lmax, gg);
        }

        for (int o = 16; o; o >>= 1) {
            lmin = fminf(lmin, __shfl_xor_sync(0xFFFFFFFFu, lmin, o));
            lmax = fmaxf(lmax, __shfl_xor_sync(0xFFFFFFFFu, lmax, o));
        }
        int wid = t >> 5, lid = t & 31;
        if (lid == 0) { smin[wid] = lmin; smax[wid] = lmax; }
        __syncthreads();
        if (t == 0) {
            float bmin = smin[0], bmax = smax[0];
            #pragma unroll
            for (int i = 1; i < (TB >> 5); i++) {
                bmin = fminf(bmin, smin[i]);
                bmax = fmaxf(bmax, smax[i]);
            }
            atomicMin(&g_min_bits, f_enc(bmin));
            atomicMax(&g_max_bits, f_enc(bmax));
        }
    }

    grid_barrier(1u * G);

    // ================= phase 2: histogram (2x ILP) ======================
    {
        for (int i = t; i < 256 * 8; i += TB) sh.hist[i] = 0u;
        __syncthreads();

        const float vmin = f_dec(*((volatile unsigned int*)&g_min_bits));
        const float vmax = f_dec(*((volatile unsigned int*)&g_max_bits));
        const float scale = 256.0f / (vmax - vmin);

        unsigned int* my = sh.hist + ((t >> 5) & 7) * 256;
        const float4* __restrict__ gr4 = (const float4*)g_gray;

        int g = blockIdx.x * TB + t;
        for (; g + gstride < ngroups; g += 2 * gstride) {
            float4 vA = __ldcg(&gr4[g]);
            float4 vB = __ldcg(&gr4[g + gstride]);
            int a0 = min(255, max(0, (int)((vA.x - vmin) * scale)));
            int a1 = min(255, max(0, (int)((vA.y - vmin) * scale)));
            int a2 = min(255, max(0, (int)((vA.z - vmin) * scale)));
            int a3 = min(255, max(0, (int)((vA.w - vmin) * scale)));
            int b0 = min(255, max(0, (int)((vB.x - vmin) * scale)));
            int b1 = min(255, max(0, (int)((vB.y - vmin) * scale)));
            int b2 = min(255, max(0, (int)((vB.z - vmin) * scale)));
            int b3 = min(255, max(0, (int)((vB.w - vmin) * scale)));
            atomicAdd(&my[a0], 1u); atomicAdd(&my[a1], 1u);
            atomicAdd(&my[a2], 1u); atomicAdd(&my[a3], 1u);
            atomicAdd(&my[b0], 1u); atomicAdd(&my[b1], 1u);
            atomicAdd(&my[b2], 1u); atomicAdd(&my[b3], 1u);
        }
        for (; g < ngroups; g += gstride) {
            float4 v = __ldcg(&gr4[g]);
            int b0 = min(255, max(0, (int)((v.x - vmin) * scale)));
            int b1 = min(255, max(0, (int)((v.y - vmin) * scale)));
            int b2 = min(255, max(0, (int)((v.z - vmin) * scale)));
            int b3 = min(255, max(0, (int)((v.w - vmin) * scale)));
            atomicAdd(&my[b0], 1u); atomicAdd(&my[b1], 1u);
            atomicAdd(&my[b2], 1u); atomicAdd(&my[b3], 1u);
        }
        for (int p = (ngroups << 2) + blockIdx.x * TB + t; p < npix; p += gstride) {
            int b = min(255, max(0, (int)((__ldcg(&g_gray[p]) - vmin) * scale)));
            atomicAdd(&my[b], 1u);
        }
        __syncthreads();
        for (int i = t; i < 256; i += TB) {
            unsigned int s = 0;
            #pragma unroll
            for (int r = 0; r < 8; r++) s += sh.hist[r * 256 + i];
            if (s) atomicAdd(&g_hist[i], s);
        }
    }

    grid_barrier(2u * G);

    // ========== phase 3: Otsu — redundant per block (no 3rd barrier) =====
    {
        const float vmin = f_dec(g_min_bits);
        const float vmax = f_dec(g_max_bits);
        const float step = __fmul_rn(__fadd_rn(vmax, -vmin), 1.0f / 256.0f);

        float e0 = __fadd_rn(vmin, __fmul_rn(step, (float)t));
        float e1 = (t == 255) ? vmax : __fadd_rn(vmin, __fmul_rn(step, (float)(t + 1)));
        float ct = __fmul_rn(__fadd_rn(e0, e1), 0.5f);
        sh.o.c[t] = ct;

        float hv = (float)__ldcg(&g_hist[t]);
        float hc = __fmul_rn(hv, ct);
        sh.o.w1[t] = hv; sh.o.s1[t] = hc;
        sh.o.w2[t] = hv; sh.o.s2[t] = hc;
        __syncthreads();

        #pragma unroll
        for (int s = 1; s < 256; s <<= 1) {
            float aw1 = (t >= s)      ? sh.o.w1[t - s] : 0.0f;
            float as1 = (t >= s)      ? sh.o.s1[t - s] : 0.0f;
            float aw2 = (t + s < 256) ? sh.o.w2[t + s] : 0.0f;
            float as2 = (t + s < 256) ? sh.o.s2[t + s] : 0.0f;
            __syncthreads();
            sh.o.w1[t] = __fadd_rn(sh.o.w1[t], aw1);
            sh.o.s1[t] = __fadd_rn(sh.o.s1[t], as1);
            sh.o.w2[t] = __fadd_rn(sh.o.w2[t], aw2);
            sh.o.s2[t] = __fadd_rn(sh.o.s2[t], as2);
            __syncthreads();
        }

        float v = -CUDART_INF_F;
        if (t < 255) {
            float m1 = sh.o.s1[t] / fmaxf(sh.o.w1[t], 1.0f);
            float m2 = sh.o.s2[t + 1] / fmaxf(sh.o.w2[t + 1], 1.0f);
            float d = __fadd_rn(m1, -m2);
            v = __fmul_rn(__fmul_rn(sh.o.w1[t], sh.o.w2[t + 1]), __fmul_rn(d, d));
        }
        sh.o.bv[t] = v; sh.o.bi[t] = t;
        __syncthreads();
        for (int s = 128; s; s >>= 1) {
            if (t < s) {
                float ov = sh.o.bv[t + s]; int oi = sh.o.bi[t + s];
                if (ov > sh.o.bv[t] || (ov == sh.o.bv[t] && oi < sh.o.bi[t])) {
                    sh.o.bv[t] = ov; sh.o.bi[t] = oi;
                }
            }
            __syncthreads();
        }
        if (t == 0) s_thresh = sh.o.c[sh.o.bi[0]];
        __syncthreads();
    }

    // ========== phase 4: direct binarize + tile (4x ILP) ================
    {
        const float thr = s_thresh;
        const int nout4 = (npix * 3) >> 2;
        const float* __restrict__ gray = g_gray;
        float4* __restrict__ o4 = (float4*)out;

        int f = blockIdx.x * TB + t;
        for (; f + 3 * gstride < nout4; f += 4 * gstride) {
            #pragma unroll
            for (int u = 0; u < 4; u++) {
                const int fu = f + u * gstride;
                const int e0 = 4 * fu;
                const int p0 = e0 / 3;
                const int r  = e0 - 3 * p0;
                float ga = __ldcg(&gray[p0]);
                float gb = __ldcg(&gray[p0 + 1]);
                float ba = (ga > thr) ? 1.0f : 0.0f;
                float bb = (gb > thr) ? 1.0f : 0.0f;
                float4 v;
                v.x = ba;
                v.y = (r < 2) ? ba : bb;
                v.z = (r < 1) ? ba : bb;
                v.w = bb;
                o4[fu] = v;
            }
        }
        for (; f < nout4; f += gstride) {
            const int e0 = 4 * f;
            const int p0 = e0 / 3;
            const int r  = e0 - 3 * p0;
            float ga = __ldcg(&gray[p0]);
            float gb = __ldcg(&gray[p0 + 1]);
            float ba = (ga > thr) ? 1.0f : 0.0f;
            float bb = (gb > thr) ? 1.0f : 0.0f;
            float4 v;
            v.x = ba;
            v.y = (r < 2) ? ba : bb;
            v.z = (r < 1) ? ba : bb;
            v.w = bb;
            o4[f] = v;
        }
        for (int e = (nout4 << 2) + blockIdx.x * TB + t; e < npix * 3; e += gstride) {
            float g = __ldcg(&gray[e / 3]);
            out[e] = (g > thr) ? 1.0f : 0.0f;
        }
    }
}

// ---------------- launch ---------------------------------------------------
extern "C" void kernel_launch(void* const* d_in, const int* in_sizes, int n_in,
                              void* d_out, int out_size) {
    const float* in = (const float*)d_in[0];
    float* out = (float*)d_out;
    int npix = in_sizes[0] / 3;

    init_kernel<<<1, 256>>>();
    fused_kernel<<<GRID, TB>>>(in, out, npix);
}

// round 15
// speedup vs baseline: 1.2468x; 1.2468x over previous
#include <cuda_runtime.h>
#include <math_constants.h>

#define NPIX_MAX (32 * 128 * 2048)
#define TB   256
#define GRID (148 * 8)   // 1184

__device__ float        g_gray[NPIX_MAX];
__device__ unsigned int g_min_bits = 0xFFFFFFFFu;   // reset by hist last-block each run
__device__ unsigned int g_max_bits = 0x00000000u;
__device__ unsigned int g_hist[256];                // zero-init; reset by hist last-block
__device__ unsigned int g_done = 0u;                // last-block counter; self-resetting
__device__ float        g_thresh;

__device__ __forceinline__ unsigned int f_enc(float f) {
    unsigned int u = __float_as_uint(f);
    return (u & 0x80000000u) ? ~u : (u | 0x80000000u);
}
__device__ __forceinline__ float f_dec(unsigned int e) {
    unsigned int u = (e & 0x80000000u) ? (e & 0x7FFFFFFFu) : ~e;
    return __uint_as_float(u);
}
__device__ __forceinline__ float gray_of(float r, float g, float b) {
    return fmaf(0.1140f, b, fmaf(0.5870f, g, __fmul_rn(0.2989f, r)));
}

// ---------------- K1: gray + min/max (smem-staged coalesced loads) ---------
__global__ void gray_minmax_kernel(const float* __restrict__ in, int npix) {
    __shared__ float4 stage[TB * 3];            // 12 KB
    const int ngroups = npix >> 2;
    const int nf4     = ngroups * 3;
    const int ntiles  = (ngroups + TB - 1) / TB;
    const float4* __restrict__ in4 = (const float4*)in;
    float4* __restrict__ gr4 = (float4*)g_gray;
    const int t = threadIdx.x;

    float lmin = CUDART_INF_F, lmax = -CUDART_INF_F;

    for (int tile = blockIdx.x; tile < ntiles; tile += gridDim.x) {
        const int gbase = tile * TB;
        const int fbase = gbase * 3;
        #pragma unroll
        for (int j = 0; j < 3; j++) {
            int idx = t + j * TB;
            if (fbase + idx < nf4) stage[idx] = in4[fbase + idx];
        }
        __syncthreads();
        const int g = gbase + t;
        if (g < ngroups) {
            float4 a = stage[3 * t + 0];
            float4 b = stage[3 * t + 1];
            float4 c = stage[3 * t + 2];
            float g0 = gray_of(a.x, a.y, a.z);
            float g1 = gray_of(a.w, b.x, b.y);
            float g2 = gray_of(b.z, b.w, c.x);
            float g3 = gray_of(c.y, c.z, c.w);
            gr4[g] = make_float4(g0, g1, g2, g3);
            lmin = fminf(lmin, fminf(fminf(g0, g1), fminf(g2, g3)));
            lmax = fmaxf(lmax, fmaxf(fmaxf(g0, g1), fmaxf(g2, g3)));
        }
        __syncthreads();
    }
    const int stride = gridDim.x * blockDim.x;
    for (int p = (ngroups << 2) + blockIdx.x * blockDim.x + t; p < npix; p += stride) {
        float gg = gray_of(in[3 * p], in[3 * p + 1], in[3 * p + 2]);
        g_gray[p] = gg;
        lmin = fminf(lmin, gg);
        lmax = fmaxf(lmax, gg);
    }

    for (int o = 16; o; o >>= 1) {
        lmin = fminf(lmin, __shfl_xor_sync(0xFFFFFFFFu, lmin, o));
        lmax = fmaxf(lmax, __shfl_xor_sync(0xFFFFFFFFu, lmax, o));
    }
    __shared__ float smin[8], smax[8];
    int wid = t >> 5, lid = t & 31;
    if (lid == 0) { smin[wid] = lmin; smax[wid] = lmax; }
    __syncthreads();
    if (t == 0) {
        float bmin = smin[0], bmax = smax[0];
        #pragma unroll
        for (int i = 1; i < (TB >> 5); i++) {
            bmin = fminf(bmin, smin[i]);
            bmax = fmaxf(bmax, smax[i]);
        }
        atomicMin(&g_min_bits, f_enc(bmin));
        atomicMax(&g_max_bits, f_enc(bmax));
    }
}

// ------- K2: histogram (2x ILP) + last-block Otsu + state reset ------------
struct HistShared {
    union {
        unsigned int hist[256 * 8];   // 8 KB (accumulation)
        struct {
            float c[256], w1[256], s1[256], w2[256], s2[256], bv[256];
            int bi[256];
        } o;                           // 7 KB (last-block otsu)
    };
};

__global__ void hist_kernel(int npix) {
    __shared__ HistShared sh;
    __shared__ unsigned int s_last;
    const int t = threadIdx.x;

    // prologue overlaps K1 tail under PDL
    for (int i = t; i < 256 * 8; i += TB) sh.hist[i] = 0u;
    __syncthreads();

    cudaGridDependencySynchronize();   // wait for K1 results

    const float vmin = f_dec(g_min_bits);
    const float vmax = f_dec(g_max_bits);
    const float scale = 256.0f / (vmax - vmin);

    unsigned int* my = sh.hist + ((t >> 5) & 7) * 256;
    const int ngroups = npix >> 2;
    const int stride  = gridDim.x * blockDim.x;
    const float4* __restrict__ gr4 = (const float4*)g_gray;

    int g = blockIdx.x * TB + t;
    for (; g + stride < ngroups; g += 2 * stride) {
        float4 vA = __ldcg(&gr4[g]);
        float4 vB = __ldcg(&gr4[g + stride]);
        int a0 = min(255, max(0, (int)((vA.x - vmin) * scale)));
        int a1 = min(255, max(0, (int)((vA.y - vmin) * scale)));
        int a2 = min(255, max(0, (int)((vA.z - vmin) * scale)));
        int a3 = min(255, max(0, (int)((vA.w - vmin) * scale)));
        int b0 = min(255, max(0, (int)((vB.x - vmin) * scale)));
        int b1 = min(255, max(0, (int)((vB.y - vmin) * scale)));
        int b2 = min(255, max(0, (int)((vB.z - vmin) * scale)));
        int b3 = min(255, max(0, (int)((vB.w - vmin) * scale)));
        atomicAdd(&my[a0], 1u); atomicAdd(&my[a1], 1u);
        atomicAdd(&my[a2], 1u); atomicAdd(&my[a3], 1u);
        atomicAdd(&my[b0], 1u); atomicAdd(&my[b1], 1u);
        atomicAdd(&my[b2], 1u); atomicAdd(&my[b3], 1u);
    }
    for (; g < ngroups; g += stride) {
        float4 v = __ldcg(&gr4[g]);
        int b0 = min(255, max(0, (int)((v.x - vmin) * scale)));
        int b1 = min(255, max(0, (int)((v.y - vmin) * scale)));
        int b2 = min(255, max(0, (int)((v.z - vmin) * scale)));
        int b3 = min(255, max(0, (int)((v.w - vmin) * scale)));
        atomicAdd(&my[b0], 1u); atomicAdd(&my[b1], 1u);
        atomicAdd(&my[b2], 1u); atomicAdd(&my[b3], 1u);
    }
    for (int p = (ngroups << 2) + blockIdx.x * TB + t; p < npix; p += stride) {
        int b = min(255, max(0, (int)((__ldcg(&g_gray[p]) - vmin) * scale)));
        atomicAdd(&my[b], 1u);
    }
    __syncthreads();
    for (int i = t; i < 256; i += TB) {
        unsigned int s = 0;
        #pragma unroll
        for (int r = 0; r < 8; r++) s += sh.hist[r * 256 + i];
        if (s) atomicAdd(&g_hist[i], s);
    }

    // ---- last-block-done: Otsu threshold + state reset ----
    __threadfence();
    if (t == 0) s_last = (atomicAdd(&g_done, 1u) == (unsigned)gridDim.x - 1u) ? 1u : 0u;
    __syncthreads();
    if (s_last) {
        __threadfence();

        const float step = __fmul_rn(__fadd_rn(vmax, -vmin), 1.0f / 256.0f);
        float e0 = __fadd_rn(vmin, __fmul_rn(step, (float)t));
        float e1 = (t == 255) ? vmax : __fadd_rn(vmin, __fmul_rn(step, (float)(t + 1)));
        float ct = __fmul_rn(__fadd_rn(e0, e1), 0.5f);

        float hv = (float)g_hist[t];
        g_hist[t] = 0u;                      // reset for next replay
        if (t == 0) {
            g_min_bits = 0xFFFFFFFFu;
            g_max_bits = 0x00000000u;
            g_done     = 0u;
        }
        __syncthreads();                     // smem union switch

        sh.o.c[t] = ct;
        float hc = __fmul_rn(hv, ct);
        sh.o.w1[t] = hv; sh.o.s1[t] = hc;
        sh.o.w2[t] = hv; sh.o.s2[t] = hc;
        __syncthreads();

        #pragma unroll
        for (int s = 1; s < 256; s <<= 1) {
            float aw1 = (t >= s)      ? sh.o.w1[t - s] : 0.0f;
            float as1 = (t >= s)      ? sh.o.s1[t - s] : 0.0f;
            float aw2 = (t + s < 256) ? sh.o.w2[t + s] : 0.0f;
            float as2 = (t + s < 256) ? sh.o.s2[t + s] : 0.0f;
            __syncthreads();
            sh.o.w1[t] = __fadd_rn(sh.o.w1[t], aw1);
            sh.o.s1[t] = __fadd_rn(sh.o.s1[t], as1);
            sh.o.w2[t] = __fadd_rn(sh.o.w2[t], aw2);
            sh.o.s2[t] = __fadd_rn(sh.o.s2[t], as2);
            __syncthreads();
        }

        float v = -CUDART_INF_F;
        if (t < 255) {
            float m1 = sh.o.s1[t] / fmaxf(sh.o.w1[t], 1.0f);
            float m2 = sh.o.s2[t + 1] / fmaxf(sh.o.w2[t + 1], 1.0f);
            float d = __fadd_rn(m1, -m2);
            v = __fmul_rn(__fmul_rn(sh.o.w1[t], sh.o.w2[t + 1]), __fmul_rn(d, d));
        }
        sh.o.bv[t] = v; sh.o.bi[t] = t;
        __syncthreads();
        for (int s = 128; s; s >>= 1) {
            if (t < s) {
                float ov = sh.o.bv[t + s]; int oi = sh.o.bi[t + s];
                if (ov > sh.o.bv[t] || (ov == sh.o.bv[t] && oi < sh.o.bi[t])) {
                    sh.o.bv[t] = ov; sh.o.bi[t] = oi;
                }
            }
            __syncthreads();
        }
        if (t == 0) g_thresh = sh.o.c[sh.o.bi[0]];
    }
}

// ---------------- K3: direct binarize + tile (4x ILP) ----------------------
__global__ void binarize_kernel(float* __restrict__ out, int npix) {
    cudaGridDependencySynchronize();   // wait for g_thresh

    const float thr = g_thresh;
    const int nout4 = (npix * 3) >> 2;
    const int stride = gridDim.x * blockDim.x;
    const float* __restrict__ gray = g_gray;
    float4* __restrict__ o4 = (float4*)out;
    const int t = threadIdx.x;

    int f = blockIdx.x * blockDim.x + t;
    for (; f + 3 * stride < nout4; f += 4 * stride) {
        #pragma unroll
        for (int u = 0; u < 4; u++) {
            const int fu = f + u * stride;
            const int e0 = 4 * fu;
            const int p0 = e0 / 3;
            const int r  = e0 - 3 * p0;
            float ga = __ldg(&gray[p0]);
            float gb = __ldg(&gray[p0 + 1]);
            float ba = (ga > thr) ? 1.0f : 0.0f;
            float bb = (gb > thr) ? 1.0f : 0.0f;
            float4 v;
            v.x = ba;
            v.y = (r < 2) ? ba : bb;
            v.z = (r < 1) ? ba : bb;
            v.w = bb;
            o4[fu] = v;
        }
    }
    for (; f < nout4; f += stride) {
        const int e0 = 4 * f;
        const int p0 = e0 / 3;
        const int r  = e0 - 3 * p0;
        float ga = __ldg(&gray[p0]);
        float gb = __ldg(&gray[p0 + 1]);
        float ba = (ga > thr) ? 1.0f : 0.0f;
        float bb = (gb > thr) ? 1.0f : 0.0f;
        float4 v;
        v.x = ba;
        v.y = (r < 2) ? ba : bb;
        v.z = (r < 1) ? ba : bb;
        v.w = bb;
        o4[f] = v;
    }
    for (int e = (nout4 << 2) + blockIdx.x * blockDim.x + t; e < npix * 3; e += stride) {
        float g = __ldg(&gray[e / 3]);
        out[e] = (g > thr) ? 1.0f : 0.0f;
    }
}

// ---------------- launch (PDL on dependent kernels) ------------------------
extern "C" void kernel_launch(void* const* d_in, const int* in_sizes, int n_in,
                              void* d_out, int out_size) {
    const float* in = (const float*)d_in[0];
    float* out = (float*)d_out;
    int npix = in_sizes[0] / 3;

    gray_minmax_kernel<<<GRID, TB>>>(in, npix);

    cudaLaunchAttribute attrs[1];
    attrs[0].id = cudaLaunchAttributeProgrammaticStreamSerialization;
    attrs[0].val.programmaticStreamSerializationAllowed = 1;

    cudaLaunchConfig_t cfg = {};
    cfg.gridDim = dim3(GRID);
    cfg.blockDim = dim3(TB);
    cfg.dynamicSmemBytes = 0;
    cfg.stream = 0;
    cfg.attrs = attrs;
    cfg.numAttrs = 1;

    cudaLaunchKernelEx(&cfg, hist_kernel, npix);
    cudaLaunchKernelEx(&cfg, binarize_kernel, out, npix);
}

// round 16
// speedup vs baseline: 1.2517x; 1.0039x over previous
#include <cuda_runtime.h>
#include <math_constants.h>

#define NPIX_MAX (32 * 128 * 2048)
#define TB   256
#define GRID (148 * 8)   // 1184

__device__ float        g_gray[NPIX_MAX];
__device__ unsigned int g_min_bits = 0xFFFFFFFFu;   // reset by hist last-block each run
__device__ unsigned int g_max_bits = 0x00000000u;
__device__ unsigned int g_hist[256];                // zero-init; reset by hist last-block
__device__ unsigned int g_done = 0u;                // last-block counter; self-resetting
__device__ float        g_thresh;

__device__ __forceinline__ unsigned int f_enc(float f) {
    unsigned int u = __float_as_uint(f);
    return (u & 0x80000000u) ? ~u : (u | 0x80000000u);
}
__device__ __forceinline__ float f_dec(unsigned int e) {
    unsigned int u = (e & 0x80000000u) ? (e & 0x7FFFFFFFu) : ~e;
    return __uint_as_float(u);
}
__device__ __forceinline__ float gray_of(float r, float g, float b) {
    return fmaf(0.1140f, b, fmaf(0.5870f, g, __fmul_rn(0.2989f, r)));
}

// ---------------- K1: gray + min/max (smem-staged coalesced loads) ---------
__global__ void gray_minmax_kernel(const float* __restrict__ in, int npix) {
    __shared__ float4 stage[TB * 3];            // 12 KB
    const int ngroups = npix >> 2;
    const int nf4     = ngroups * 3;
    const int ntiles  = (ngroups + TB - 1) / TB;
    const float4* __restrict__ in4 = (const float4*)in;
    float4* __restrict__ gr4 = (float4*)g_gray;
    const int t = threadIdx.x;

    float lmin = CUDART_INF_F, lmax = -CUDART_INF_F;

    for (int tile = blockIdx.x; tile < ntiles; tile += gridDim.x) {
        const int gbase = tile * TB;
        const int fbase = gbase * 3;
        #pragma unroll
        for (int j = 0; j < 3; j++) {
            int idx = t + j * TB;
            if (fbase + idx < nf4) stage[idx] = in4[fbase + idx];
        }
        __syncthreads();
        const int g = gbase + t;
        if (g < ngroups) {
            float4 a = stage[3 * t + 0];
            float4 b = stage[3 * t + 1];
            float4 c = stage[3 * t + 2];
            float g0 = gray_of(a.x, a.y, a.z);
            float g1 = gray_of(a.w, b.x, b.y);
            float g2 = gray_of(b.z, b.w, c.x);
            float g3 = gray_of(c.y, c.z, c.w);
            gr4[g] = make_float4(g0, g1, g2, g3);
            lmin = fminf(lmin, fminf(fminf(g0, g1), fminf(g2, g3)));
            lmax = fmaxf(lmax, fmaxf(fmaxf(g0, g1), fmaxf(g2, g3)));
        }
        __syncthreads();
    }
    const int stride = gridDim.x * blockDim.x;
    for (int p = (ngroups << 2) + blockIdx.x * blockDim.x + t; p < npix; p += stride) {
        float gg = gray_of(in[3 * p], in[3 * p + 1], in[3 * p + 2]);
        g_gray[p] = gg;
        lmin = fminf(lmin, gg);
        lmax = fmaxf(lmax, gg);
    }

    for (int o = 16; o; o >>= 1) {
        lmin = fminf(lmin, __shfl_xor_sync(0xFFFFFFFFu, lmin, o));
        lmax = fmaxf(lmax, __shfl_xor_sync(0xFFFFFFFFu, lmax, o));
    }
    __shared__ float smin[8], smax[8];
    int wid = t >> 5, lid = t & 31;
    if (lid == 0) { smin[wid] = lmin; smax[wid] = lmax; }
    __syncthreads();
    if (t == 0) {
        float bmin = smin[0], bmax = smax[0];
        #pragma unroll
        for (int i = 1; i < (TB >> 5); i++) {
            bmin = fminf(bmin, smin[i]);
            bmax = fmaxf(bmax, smax[i]);
        }
        atomicMin(&g_min_bits, f_enc(bmin));
        atomicMax(&g_max_bits, f_enc(bmax));
    }
}

// ------- K2: histogram (4x ILP) + last-block Otsu + state reset ------------
struct HistShared {
    union {
        unsigned int hist[256 * 8];   // 8 KB (accumulation)
        struct {
            float c[256], w1[256], s1[256], w2[256], s2[256], bv[256];
            int bi[256];
        } o;                           // 7 KB (last-block otsu)
    };
};

__global__ void hist_kernel(int npix) {
    __shared__ HistShared sh;
    __shared__ unsigned int s_last;
    const int t = threadIdx.x;

    // prologue overlaps K1 tail under PDL
    for (int i = t; i < 256 * 8; i += TB) sh.hist[i] = 0u;
    __syncthreads();

    cudaGridDependencySynchronize();   // wait for K1 results

    const float vmin = f_dec(g_min_bits);
    const float vmax = f_dec(g_max_bits);
    const float scale = 256.0f / (vmax - vmin);

    unsigned int* my = sh.hist + ((t >> 5) & 7) * 256;
    const int ngroups = npix >> 2;
    const int stride  = gridDim.x * blockDim.x;
    const float4* __restrict__ gr4 = (const float4*)g_gray;

    int g = blockIdx.x * TB + t;
    for (; g + 3 * stride < ngroups; g += 4 * stride) {
        float4 v0 = __ldcg(&gr4[g]);
        float4 v1 = __ldcg(&gr4[g + stride]);
        float4 v2 = __ldcg(&gr4[g + 2 * stride]);
        float4 v3 = __ldcg(&gr4[g + 3 * stride]);
        #pragma unroll
        for (int u = 0; u < 4; u++) {
            float4 v = (u == 0) ? v0 : (u == 1) ? v1 : (u == 2) ? v2 : v3;
            int b0 = min(255, max(0, (int)((v.x - vmin) * scale)));
            int b1 = min(255, max(0, (int)((v.y - vmin) * scale)));
            int b2 = min(255, max(0, (int)((v.z - vmin) * scale)));
            int b3 = min(255, max(0, (int)((v.w - vmin) * scale)));
            atomicAdd(&my[b0], 1u); atomicAdd(&my[b1], 1u);
            atomicAdd(&my[b2], 1u); atomicAdd(&my[b3], 1u);
        }
    }
    for (; g < ngroups; g += stride) {
        float4 v = __ldcg(&gr4[g]);
        int b0 = min(255, max(0, (int)((v.x - vmin) * scale)));
        int b1 = min(255, max(0, (int)((v.y - vmin) * scale)));
        int b2 = min(255, max(0, (int)((v.z - vmin) * scale)));
        int b3 = min(255, max(0, (int)((v.w - vmin) * scale)));
        atomicAdd(&my[b0], 1u); atomicAdd(&my[b1], 1u);
        atomicAdd(&my[b2], 1u); atomicAdd(&my[b3], 1u);
    }
    for (int p = (ngroups << 2) + blockIdx.x * TB + t; p < npix; p += stride) {
        int b = min(255, max(0, (int)((__ldcg(&g_gray[p]) - vmin) * scale)));
        atomicAdd(&my[b], 1u);
    }
    __syncthreads();
    for (int i = t; i < 256; i += TB) {
        unsigned int s = 0;
        #pragma unroll
        for (int r = 0; r < 8; r++) s += sh.hist[r * 256 + i];
        if (s) atomicAdd(&g_hist[i], s);
    }

    // ---- last-block-done: Otsu threshold + state reset ----
    __threadfence();
    if (t == 0) s_last = (atomicAdd(&g_done, 1u) == (unsigned)gridDim.x - 1u) ? 1u : 0u;
    __syncthreads();
    if (s_last) {
        __threadfence();

        const float step = __fmul_rn(__fadd_rn(vmax, -vmin), 1.0f / 256.0f);
        float e0 = __fadd_rn(vmin, __fmul_rn(step, (float)t));
        float e1 = (t == 255) ? vmax : __fadd_rn(vmin, __fmul_rn(step, (float)(t + 1)));
        float ct = __fmul_rn(__fadd_rn(e0, e1), 0.5f);

        float hv = (float)g_hist[t];
        g_hist[t] = 0u;                      // reset for next replay
        if (t == 0) {
            g_min_bits = 0xFFFFFFFFu;
            g_max_bits = 0x00000000u;
            g_done     = 0u;
        }
        __syncthreads();                     // smem union switch

        sh.o.c[t] = ct;
        float hc = __fmul_rn(hv, ct);
        sh.o.w1[t] = hv; sh.o.s1[t] = hc;
        sh.o.w2[t] = hv; sh.o.s2[t] = hc;
        __syncthreads();

        #pragma unroll
        for (int s = 1; s < 256; s <<= 1) {
            float aw1 = (t >= s)      ? sh.o.w1[t - s] : 0.0f;
            float as1 = (t >= s)      ? sh.o.s1[t - s] : 0.0f;
            float aw2 = (t + s < 256) ? sh.o.w2[t + s] : 0.0f;
            float as2 = (t + s < 256) ? sh.o.s2[t + s] : 0.0f;
            __syncthreads();
            sh.o.w1[t] = __fadd_rn(sh.o.w1[t], aw1);
            sh.o.s1[t] = __fadd_rn(sh.o.s1[t], as1);
            sh.o.w2[t] = __fadd_rn(sh.o.w2[t], aw2);
            sh.o.s2[t] = __fadd_rn(sh.o.s2[t], as2);
            __syncthreads();
        }

        float v = -CUDART_INF_F;
        if (t < 255) {
            float m1 = sh.o.s1[t] / fmaxf(sh.o.w1[t], 1.0f);
            float m2 = sh.o.s2[t + 1] / fmaxf(sh.o.w2[t + 1], 1.0f);
            float d = __fadd_rn(m1, -m2);
            v = __fmul_rn(__fmul_rn(sh.o.w1[t], sh.o.w2[t + 1]), __fmul_rn(d, d));
        }
        sh.o.bv[t] = v; sh.o.bi[t] = t;
        __syncthreads();
        for (int s = 128; s; s >>= 1) {
            if (t < s) {
                float ov = sh.o.bv[t + s]; int oi = sh.o.bi[t + s];
                if (ov > sh.o.bv[t] || (ov == sh.o.bv[t] && oi < sh.o.bi[t])) {
                    sh.o.bv[t] = ov; sh.o.bi[t] = oi;
                }
            }
            __syncthreads();
        }
        if (t == 0) g_thresh = sh.o.c[sh.o.bi[0]];
    }
}

// ---------------- K3: direct binarize + tile (6x ILP) ----------------------
__global__ void binarize_kernel(float* __restrict__ out, int npix) {
    cudaGridDependencySynchronize();   // wait for g_thresh

    const float thr = g_thresh;
    const int nout4 = (npix * 3) >> 2;
    const int stride = gridDim.x * blockDim.x;
    const float* __restrict__ gray = g_gray;
    float4* __restrict__ o4 = (float4*)out;
    const int t = threadIdx.x;

    int f = blockIdx.x * blockDim.x + t;
    for (; f + 5 * stride < nout4; f += 6 * stride) {
        #pragma unroll
        for (int u = 0; u < 6; u++) {
            const int fu = f + u * stride;
            const int e0 = 4 * fu;
            const int p0 = e0 / 3;
            const int r  = e0 - 3 * p0;
            float ga = __ldg(&gray[p0]);
            float gb = __ldg(&gray[p0 + 1]);
            float ba = (ga > thr) ? 1.0f : 0.0f;
            float bb = (gb > thr) ? 1.0f : 0.0f;
            float4 v;
            v.x = ba;
            v.y = (r < 2) ? ba : bb;
            v.z = (r < 1) ? ba : bb;
            v.w = bb;
            o4[fu] = v;
        }
    }
    for (; f < nout4; f += stride) {
        const int e0 = 4 * f;
        const int p0 = e0 / 3;
        const int r  = e0 - 3 * p0;
        float ga = __ldg(&gray[p0]);
        float gb = __ldg(&gray[p0 + 1]);
        float ba = (ga > thr) ? 1.0f : 0.0f;
        float bb = (gb > thr) ? 1.0f : 0.0f;
        float4 v;
        v.x = ba;
        v.y = (r < 2) ? ba : bb;
        v.z = (r < 1) ? ba : bb;
        v.w = bb;
        o4[f] = v;
    }
    for (int e = (nout4 << 2) + blockIdx.x * blockDim.x + t; e < npix * 3; e += stride) {
        float g = __ldg(&gray[e / 3]);
        out[e] = (g > thr) ? 1.0f : 0.0f;
    }
}

// ---------------- launch (PDL on dependent kernels) ------------------------
extern "C" void kernel_launch(void* const* d_in, const int* in_sizes, int n_in,
                              void* d_out, int out_size) {
    const float* in = (const float*)d_in[0];
    float* out = (float*)d_out;
    int npix = in_sizes[0] / 3;

    gray_minmax_kernel<<<GRID, TB>>>(in, npix);

    cudaLaunchAttribute attrs[1];
    attrs[0].id = cudaLaunchAttributeProgrammaticStreamSerialization;
    attrs[0].val.programmaticStreamSerializationAllowed = 1;

    cudaLaunchConfig_t cfg = {};
    cfg.gridDim = dim3(GRID);
    cfg.blockDim = dim3(TB);
    cfg.dynamicSmemBytes = 0;
    cfg.stream = 0;
    cfg.attrs = attrs;
    cfg.numAttrs = 1;

    cudaLaunchKernelEx(&cfg, hist_kernel, npix);
    cudaLaunchKernelEx(&cfg, binarize_kernel, out, npix);
}